// round 1
// baseline (speedup 1.0000x reference)
#include <cuda_runtime.h>
#include <cuda_bf16.h>
#include <math.h>

// ---------------- problem constants ----------------
#define EMBED   768
#define DEPTH   12
#define HEADS   12
#define HEAD_DIM 64
#define HIDDEN  3072
#define PATCH   16
#define BATCH   64
#define NTOK    198          // 1 local + 1 cls + 196 patches
#define NPATCH  196
#define TOKENS  (BATCH*NTOK)     // 12672
#define PROWS   (BATCH*NPATCH)   // 12544
#define SCALE_F 0.125f           // 64^-0.5

// ---------------- scratch (static device memory; no allocations) ----------------
__device__ float g_h  [(size_t)TOKENS * EMBED];     // residual stream
__device__ float g_y  [(size_t)TOKENS * EMBED];     // LN output
__device__ float g_qkv[(size_t)TOKENS * 3 * EMBED]; // qkv
__device__ float g_att[(size_t)TOKENS * EMBED];     // attention out (b,t,h*d)
__device__ float g_hid[(size_t)TOKENS * HIDDEN];    // MLP hidden
__device__ float g_P  [(size_t)PROWS  * EMBED];     // im2col patches
__device__ float g_WT [(size_t)EMBED  * EMBED];     // conv_w transposed -> [K,N]

// ---------------- epilogue modes ----------------
#define EPI_NONE      0
#define EPI_BIAS      1
#define EPI_BIAS_RES  2
#define EPI_BIAS_GELU 3
#define EPI_PATCH     4

// ---------------- im2col ----------------
__global__ void im2col_kernel(const float* __restrict__ x, float* __restrict__ P)
{
    int bp = blockIdx.x;              // 0..12543
    int b  = bp / NPATCH;
    int p  = bp % NPATCH;
    int ph = p / 14, pw = p % 14;
    const float* xb = x + (size_t)b * 3 * 224 * 224;
    for (int j = threadIdx.x; j < EMBED; j += 256) {
        int c  = j >> 8;
        int kh = (j >> 4) & 15;
        int kw = j & 15;
        P[(size_t)bp * EMBED + j] = xb[((size_t)c * 224 + ph * 16 + kh) * 224 + pw * 16 + kw];
    }
}

// ---------------- 768x768 transpose (conv_w [N,K] -> WT [K,N]) ----------------
__global__ void transpose768_kernel(const float* __restrict__ in, float* __restrict__ out)
{
    __shared__ float t[32][33];
    int x0 = blockIdx.x * 32;
    int y0 = blockIdx.y * 32;
    for (int i = threadIdx.y; i < 32; i += 8)
        t[i][threadIdx.x] = in[(size_t)(y0 + i) * EMBED + x0 + threadIdx.x];
    __syncthreads();
    for (int i = threadIdx.y; i < 32; i += 8)
        out[(size_t)(x0 + i) * EMBED + y0 + threadIdx.x] = t[threadIdx.x][i];
}

// ---------------- local/cls token init ----------------
__global__ void init_tokens_kernel(float* __restrict__ h,
                                   const float* __restrict__ localt,
                                   const float* __restrict__ clst)
{
    int b = blockIdx.x;
    int j = threadIdx.x;   // 768 threads
    h[((size_t)b * NTOK + 0) * EMBED + j] = localt[j];
    h[((size_t)b * NTOK + 1) * EMBED + j] = clst[j];
}

// ---------------- SGEMM: C[M,N] = A[M,K] @ B[K,N], all row-major.
// 128x128 tile, BK=16, 256 threads, 8x8 microtile. Dims must be multiples of tile.
#define BM 128
#define BN 128
#define BK 16

__global__ __launch_bounds__(256, 2)
void sgemm_kernel(const float* __restrict__ A, const float* __restrict__ B,
                  float* __restrict__ C,
                  const float* __restrict__ bias,
                  const float* __restrict__ res,
                  const float* __restrict__ pos,
                  int M, int N, int K, int epi)
{
    __shared__ float As[BK][BM];
    __shared__ float Bs[BK][BN];

    int bx = blockIdx.x;            // N tile
    int by = blockIdx.y;            // M tile
    int tid = threadIdx.x;
    int tx = tid & 15;              // 0..15
    int ty = tid >> 4;              // 0..15

    const float* Aptr = A + (size_t)by * BM * K;
    const float* Bptr = B + (size_t)bx * BN;

    float acc[8][8];
    #pragma unroll
    for (int i = 0; i < 8; i++)
        #pragma unroll
        for (int j = 0; j < 8; j++) acc[i][j] = 0.f;

    for (int k0 = 0; k0 < K; k0 += BK) {
        #pragma unroll
        for (int i = 0; i < 2; i++) {
            int s = tid * 2 + i;            // 0..511
            // A: 128 rows x 4 float4
            int m  = s >> 2;
            int kq = s & 3;
            float4 va = *reinterpret_cast<const float4*>(Aptr + (size_t)m * K + k0 + kq * 4);
            As[kq * 4 + 0][m] = va.x;
            As[kq * 4 + 1][m] = va.y;
            As[kq * 4 + 2][m] = va.z;
            As[kq * 4 + 3][m] = va.w;
            // B: 16 rows x 32 float4
            int kb = s >> 5;
            int nq = s & 31;
            float4 vb = *reinterpret_cast<const float4*>(Bptr + (size_t)(k0 + kb) * N + nq * 4);
            *reinterpret_cast<float4*>(&Bs[kb][nq * 4]) = vb;
        }
        __syncthreads();

        #pragma unroll
        for (int kk = 0; kk < BK; kk++) {
            float a[8], b[8];
            float4 a0 = *reinterpret_cast<const float4*>(&As[kk][ty * 8]);
            float4 a1 = *reinterpret_cast<const float4*>(&As[kk][ty * 8 + 4]);
            float4 b0 = *reinterpret_cast<const float4*>(&Bs[kk][tx * 8]);
            float4 b1 = *reinterpret_cast<const float4*>(&Bs[kk][tx * 8 + 4]);
            a[0]=a0.x; a[1]=a0.y; a[2]=a0.z; a[3]=a0.w;
            a[4]=a1.x; a[5]=a1.y; a[6]=a1.z; a[7]=a1.w;
            b[0]=b0.x; b[1]=b0.y; b[2]=b0.z; b[3]=b0.w;
            b[4]=b1.x; b[5]=b1.y; b[6]=b1.z; b[7]=b1.w;
            #pragma unroll
            for (int i = 0; i < 8; i++)
                #pragma unroll
                for (int j = 0; j < 8; j++)
                    acc[i][j] += a[i] * b[j];
        }
        __syncthreads();
    }

    // epilogue
    #pragma unroll
    for (int i = 0; i < 8; i++) {
        int m = by * BM + ty * 8 + i;
        #pragma unroll
        for (int j = 0; j < 8; j++) {
            int n = bx * BN + tx * 8 + j;
            float v = acc[i][j];
            if (epi == EPI_PATCH) {
                int b  = m / NPATCH;
                int p  = m - b * NPATCH;
                v += bias[n] + pos[(size_t)p * EMBED + n];
                int orow = b * NTOK + 2 + p;
                C[(size_t)orow * EMBED + n] = v;
            } else {
                if (epi != EPI_NONE) v += bias[n];
                if (epi == EPI_BIAS_RES)  v += res[(size_t)m * N + n];
                if (epi == EPI_BIAS_GELU) v = 0.5f * v * (1.f + erff(v * 0.7071067811865476f));
                C[(size_t)m * N + n] = v;
            }
        }
    }
}

// ---------------- attention: one block per (b,h) ----------------
#define KVP 65   // padded row stride for K/V in smem

__global__ void attn_kernel(const float* __restrict__ qkv, float* __restrict__ out)
{
    extern __shared__ float sm[];
    float* Ks = sm;                        // 198*65
    float* Vs = Ks + NTOK * KVP;           // 198*65
    float* Qs = Vs + NTOK * KVP;           // 8*64
    float* Ps = Qs + 8 * 64;               // 8*198

    int bh = blockIdx.x;
    int b = bh / HEADS, h = bh % HEADS;
    const float* base = qkv + (size_t)b * NTOK * (3 * EMBED) + h * HEAD_DIM;

    int tid = threadIdx.x;
    for (int idx = tid; idx < NTOK * HEAD_DIM; idx += 256) {
        int t = idx >> 6, d = idx & 63;
        Ks[t * KVP + d] = base[(size_t)t * (3 * EMBED) + EMBED + d];
        Vs[t * KVP + d] = base[(size_t)t * (3 * EMBED) + 2 * EMBED + d];
    }
    __syncthreads();

    int warp = tid >> 5, lane = tid & 31;
    for (int r = warp; r < NTOK; r += 8) {
        // load scaled q row into smem
        Qs[warp * 64 + lane]      = base[(size_t)r * (3 * EMBED) + lane]      * SCALE_F;
        Qs[warp * 64 + 32 + lane] = base[(size_t)r * (3 * EMBED) + 32 + lane] * SCALE_F;
        __syncwarp();

        float s[7];
        float mx = -1e30f;
        const float* qr = Qs + warp * 64;
        #pragma unroll
        for (int c = 0; c < 7; c++) {
            int j = lane + 32 * c;
            float acc = -1e30f;
            if (j < NTOK) {
                const float* kr = Ks + j * KVP;
                acc = 0.f;
                #pragma unroll
                for (int d = 0; d < 64; d++) acc += qr[d] * kr[d];
                mx = fmaxf(mx, acc);
            }
            s[c] = acc;
        }
        #pragma unroll
        for (int o = 16; o > 0; o >>= 1) mx = fmaxf(mx, __shfl_xor_sync(0xffffffffu, mx, o));

        float sum = 0.f;
        #pragma unroll
        for (int c = 0; c < 7; c++) {
            int j = lane + 32 * c;
            if (j < NTOK) { s[c] = expf(s[c] - mx); sum += s[c]; }
            else s[c] = 0.f;
        }
        #pragma unroll
        for (int o = 16; o > 0; o >>= 1) sum += __shfl_xor_sync(0xffffffffu, sum, o);
        float inv = 1.f / sum;

        #pragma unroll
        for (int c = 0; c < 7; c++) {
            int j = lane + 32 * c;
            if (j < NTOK) Ps[warp * NTOK + j] = s[c] * inv;
        }
        __syncwarp();

        float o0 = 0.f, o1 = 0.f;
        const float* pr = Ps + warp * NTOK;
        for (int j = 0; j < NTOK; j++) {
            float p = pr[j];
            o0 += p * Vs[j * KVP + lane];
            o1 += p * Vs[j * KVP + 32 + lane];
        }
        float* op = out + ((size_t)b * NTOK + r) * EMBED + h * HEAD_DIM;
        op[lane]      = o0;
        op[lane + 32] = o1;
        __syncwarp();
    }
}

// ---------------- LayerNorm (exact two-pass variance) ----------------
__global__ void ln_kernel(const float* __restrict__ x, const float* __restrict__ w,
                          const float* __restrict__ bb, float* __restrict__ y)
{
    int row = blockIdx.x;
    const float* xr = x + (size_t)row * EMBED;
    float* yr = y + (size_t)row * EMBED;
    int tid = threadIdx.x;          // 256
    int warp = tid >> 5, lane = tid & 31;
    __shared__ float sh[8];

    float v0 = xr[tid], v1 = xr[tid + 256], v2 = xr[tid + 512];
    float s = v0 + v1 + v2;
    #pragma unroll
    for (int o = 16; o > 0; o >>= 1) s += __shfl_xor_sync(0xffffffffu, s, o);
    if (lane == 0) sh[warp] = s;
    __syncthreads();
    float ts = 0.f;
    #pragma unroll
    for (int i = 0; i < 8; i++) ts += sh[i];
    float mu = ts * (1.f / 768.f);

    float d0 = v0 - mu, d1 = v1 - mu, d2 = v2 - mu;
    float q = d0 * d0 + d1 * d1 + d2 * d2;
    #pragma unroll
    for (int o = 16; o > 0; o >>= 1) q += __shfl_xor_sync(0xffffffffu, q, o);
    __syncthreads();
    if (lane == 0) sh[warp] = q;
    __syncthreads();
    float tq = 0.f;
    #pragma unroll
    for (int i = 0; i < 8; i++) tq += sh[i];
    float inv = rsqrtf(tq * (1.f / 768.f) + 1e-5f);

    yr[tid]       = d0 * inv * w[tid]       + bb[tid];
    yr[tid + 256] = d1 * inv * w[tid + 256] + bb[tid + 256];
    yr[tid + 512] = d2 * inv * w[tid + 512] + bb[tid + 512];
}

// ---------------- host orchestration ----------------
extern "C" void kernel_launch(void* const* d_in, const int* in_sizes, int n_in,
                              void* d_out, int out_size)
{
    const float* x        = (const float*)d_in[0];
    const float* conv_w   = (const float*)d_in[1];
    const float* conv_b   = (const float*)d_in[2];
    const float* pos      = (const float*)d_in[3];
    const float* cls_tok  = (const float*)d_in[4];
    const float* loc_tok  = (const float*)d_in[5];
    const float* ln1_w    = (const float*)d_in[6];
    const float* ln1_b    = (const float*)d_in[7];
    const float* qkv_w    = (const float*)d_in[8];
    const float* proj_w   = (const float*)d_in[9];
    const float* proj_b   = (const float*)d_in[10];
    const float* ln2_w    = (const float*)d_in[11];
    const float* ln2_b    = (const float*)d_in[12];
    const float* fc1_w    = (const float*)d_in[13];
    const float* fc1_b    = (const float*)d_in[14];
    const float* fc2_w    = (const float*)d_in[15];
    const float* fc2_b    = (const float*)d_in[16];
    const float* lnf_w    = (const float*)d_in[17];
    const float* lnf_b    = (const float*)d_in[18];
    float* out = (float*)d_out;

    float *h, *y, *qkv, *att, *hid, *P, *WT;
    cudaGetSymbolAddress((void**)&h,   g_h);
    cudaGetSymbolAddress((void**)&y,   g_y);
    cudaGetSymbolAddress((void**)&qkv, g_qkv);
    cudaGetSymbolAddress((void**)&att, g_att);
    cudaGetSymbolAddress((void**)&hid, g_hid);
    cudaGetSymbolAddress((void**)&P,   g_P);
    cudaGetSymbolAddress((void**)&WT,  g_WT);

    const int ATT_SMEM = (NTOK * KVP * 2 + 8 * 64 + 8 * NTOK) * (int)sizeof(float);
    cudaFuncSetAttribute(attn_kernel, cudaFuncAttributeMaxDynamicSharedMemorySize, ATT_SMEM);

    // patch embed
    transpose768_kernel<<<dim3(24, 24), dim3(32, 8)>>>(conv_w, WT);
    im2col_kernel<<<PROWS, 256>>>(x, P);
    init_tokens_kernel<<<BATCH, EMBED>>>(h, loc_tok, cls_tok);
    sgemm_kernel<<<dim3(EMBED / BN, PROWS / BM), 256>>>(
        P, WT, h, conv_b, nullptr, pos, PROWS, EMBED, EMBED, EPI_PATCH);

    for (int l = 0; l < DEPTH; l++) {
        const float* l1w = ln1_w + (size_t)l * EMBED;
        const float* l1b = ln1_b + (size_t)l * EMBED;
        const float* qw  = qkv_w + (size_t)l * EMBED * 3 * EMBED;
        const float* pw  = proj_w + (size_t)l * EMBED * EMBED;
        const float* pb  = proj_b + (size_t)l * EMBED;
        const float* l2w = ln2_w + (size_t)l * EMBED;
        const float* l2b = ln2_b + (size_t)l * EMBED;
        const float* f1w = fc1_w + (size_t)l * EMBED * HIDDEN;
        const float* f1b = fc1_b + (size_t)l * HIDDEN;
        const float* f2w = fc2_w + (size_t)l * HIDDEN * EMBED;
        const float* f2b = fc2_b + (size_t)l * EMBED;

        ln_kernel<<<TOKENS, 256>>>(h, l1w, l1b, y);
        sgemm_kernel<<<dim3(3 * EMBED / BN, TOKENS / BM), 256>>>(
            y, qw, qkv, nullptr, nullptr, nullptr, TOKENS, 3 * EMBED, EMBED, EPI_NONE);
        attn_kernel<<<BATCH * HEADS, 256, ATT_SMEM>>>(qkv, att);
        sgemm_kernel<<<dim3(EMBED / BN, TOKENS / BM), 256>>>(
            att, pw, h, pb, h, nullptr, TOKENS, EMBED, EMBED, EPI_BIAS_RES);
        ln_kernel<<<TOKENS, 256>>>(h, l2w, l2b, y);
        sgemm_kernel<<<dim3(HIDDEN / BN, TOKENS / BM), 256>>>(
            y, f1w, hid, f1b, nullptr, nullptr, TOKENS, HIDDEN, EMBED, EPI_BIAS_GELU);
        sgemm_kernel<<<dim3(EMBED / BN, TOKENS / BM), 256>>>(
            hid, f2w, h, f2b, h, nullptr, TOKENS, EMBED, HIDDEN, EPI_BIAS_RES);
    }

    ln_kernel<<<TOKENS, 256>>>(h, lnf_w, lnf_b, out);
}

// round 2
// speedup vs baseline: 1.0018x; 1.0018x over previous
#include <cuda_runtime.h>
#include <cuda_bf16.h>
#include <math.h>

// ---------------- problem constants ----------------
#define EMBED   768
#define DEPTH   12
#define HEADS   12
#define HEAD_DIM 64
#define HIDDEN  3072
#define PATCH   16
#define BATCH   64
#define NTOK    198          // 1 local + 1 cls + 196 patches
#define NPATCH  196
#define TOKENS  (BATCH*NTOK)     // 12672
#define PROWS   (BATCH*NPATCH)   // 12544
#define SCALE_F 0.125f           // 64^-0.5

// ---------------- scratch (static device memory; no allocations) ----------------
__device__ float g_h  [(size_t)TOKENS * EMBED];     // residual stream
__device__ float g_y  [(size_t)TOKENS * EMBED];     // LN output
__device__ float g_qkv[(size_t)TOKENS * 3 * EMBED]; // qkv
__device__ float g_att[(size_t)TOKENS * EMBED];     // attention out (b,t,h*d)
__device__ float g_hid[(size_t)TOKENS * HIDDEN];    // MLP hidden
__device__ float g_P  [(size_t)PROWS  * EMBED];     // im2col patches
__device__ float g_WT [(size_t)EMBED  * EMBED];     // conv_w transposed -> [K,N]

// ---------------- epilogue modes ----------------
#define EPI_NONE      0
#define EPI_BIAS      1
#define EPI_BIAS_RES  2
#define EPI_BIAS_GELU 3
#define EPI_PATCH     4

// ---------------- im2col ----------------
__global__ void im2col_kernel(const float* __restrict__ x, float* __restrict__ P)
{
    int bp = blockIdx.x;              // 0..12543
    int b  = bp / NPATCH;
    int p  = bp % NPATCH;
    int ph = p / 14, pw = p % 14;
    const float* xb = x + (size_t)b * 3 * 224 * 224;
    for (int j = threadIdx.x; j < EMBED; j += 256) {
        int c  = j >> 8;
        int kh = (j >> 4) & 15;
        int kw = j & 15;
        P[(size_t)bp * EMBED + j] = xb[((size_t)c * 224 + ph * 16 + kh) * 224 + pw * 16 + kw];
    }
}

// ---------------- 768x768 transpose (conv_w [N,K] -> WT [K,N]) ----------------
__global__ void transpose768_kernel(const float* __restrict__ in, float* __restrict__ out)
{
    __shared__ float t[32][33];
    int x0 = blockIdx.x * 32;
    int y0 = blockIdx.y * 32;
    for (int i = threadIdx.y; i < 32; i += 8)
        t[i][threadIdx.x] = in[(size_t)(y0 + i) * EMBED + x0 + threadIdx.x];
    __syncthreads();
    for (int i = threadIdx.y; i < 32; i += 8)
        out[(size_t)(x0 + i) * EMBED + y0 + threadIdx.x] = t[threadIdx.x][i];
}

// ---------------- local/cls token init ----------------
__global__ void init_tokens_kernel(float* __restrict__ h,
                                   const float* __restrict__ localt,
                                   const float* __restrict__ clst)
{
    int b = blockIdx.x;
    int j = threadIdx.x;   // 768 threads
    h[((size_t)b * NTOK + 0) * EMBED + j] = localt[j];
    h[((size_t)b * NTOK + 1) * EMBED + j] = clst[j];
}

// ---------------- SGEMM: C[M,N] = A[M,K] @ B[K,N], all row-major.
// 128x128 tile, BK=16, 256 threads, 8x8 microtile. Dims must be multiples of tile.
#define BM 128
#define BN 128
#define BK 16

__global__ __launch_bounds__(256, 2)
void sgemm_kernel(const float* __restrict__ A, const float* __restrict__ B,
                  float* __restrict__ C,
                  const float* __restrict__ bias,
                  const float* __restrict__ res,
                  const float* __restrict__ pos,
                  int M, int N, int K, int epi)
{
    __shared__ float As[BK][BM];
    __shared__ float Bs[BK][BN];

    int bx = blockIdx.x;            // N tile
    int by = blockIdx.y;            // M tile
    int tid = threadIdx.x;
    int tx = tid & 15;              // 0..15
    int ty = tid >> 4;              // 0..15

    const float* Aptr = A + (size_t)by * BM * K;
    const float* Bptr = B + (size_t)bx * BN;

    float acc[8][8];
    #pragma unroll
    for (int i = 0; i < 8; i++)
        #pragma unroll
        for (int j = 0; j < 8; j++) acc[i][j] = 0.f;

    for (int k0 = 0; k0 < K; k0 += BK) {
        #pragma unroll
        for (int i = 0; i < 2; i++) {
            int s = tid * 2 + i;            // 0..511
            // A: 128 rows x 4 float4
            int m  = s >> 2;
            int kq = s & 3;
            float4 va = *reinterpret_cast<const float4*>(Aptr + (size_t)m * K + k0 + kq * 4);
            As[kq * 4 + 0][m] = va.x;
            As[kq * 4 + 1][m] = va.y;
            As[kq * 4 + 2][m] = va.z;
            As[kq * 4 + 3][m] = va.w;
            // B: 16 rows x 32 float4
            int kb = s >> 5;
            int nq = s & 31;
            float4 vb = *reinterpret_cast<const float4*>(Bptr + (size_t)(k0 + kb) * N + nq * 4);
            *reinterpret_cast<float4*>(&Bs[kb][nq * 4]) = vb;
        }
        __syncthreads();

        #pragma unroll
        for (int kk = 0; kk < BK; kk++) {
            float a[8], b[8];
            float4 a0 = *reinterpret_cast<const float4*>(&As[kk][ty * 8]);
            float4 a1 = *reinterpret_cast<const float4*>(&As[kk][ty * 8 + 4]);
            float4 b0 = *reinterpret_cast<const float4*>(&Bs[kk][tx * 8]);
            float4 b1 = *reinterpret_cast<const float4*>(&Bs[kk][tx * 8 + 4]);
            a[0]=a0.x; a[1]=a0.y; a[2]=a0.z; a[3]=a0.w;
            a[4]=a1.x; a[5]=a1.y; a[6]=a1.z; a[7]=a1.w;
            b[0]=b0.x; b[1]=b0.y; b[2]=b0.z; b[3]=b0.w;
            b[4]=b1.x; b[5]=b1.y; b[6]=b1.z; b[7]=b1.w;
            #pragma unroll
            for (int i = 0; i < 8; i++)
                #pragma unroll
                for (int j = 0; j < 8; j++)
                    acc[i][j] += a[i] * b[j];
        }
        __syncthreads();
    }

    // epilogue
    #pragma unroll
    for (int i = 0; i < 8; i++) {
        int m = by * BM + ty * 8 + i;
        #pragma unroll
        for (int j = 0; j < 8; j++) {
            int n = bx * BN + tx * 8 + j;
            float v = acc[i][j];
            if (epi == EPI_PATCH) {
                int b  = m / NPATCH;
                int p  = m - b * NPATCH;
                v += bias[n] + pos[(size_t)p * EMBED + n];
                int orow = b * NTOK + 2 + p;
                C[(size_t)orow * EMBED + n] = v;
            } else {
                if (epi != EPI_NONE) v += bias[n];
                if (epi == EPI_BIAS_RES)  v += res[(size_t)m * N + n];
                if (epi == EPI_BIAS_GELU) v = 0.5f * v * (1.f + erff(v * 0.7071067811865476f));
                C[(size_t)m * N + n] = v;
            }
        }
    }
}

// ---------------- attention: one block per (b,h) ----------------
#define KVP 65   // padded row stride for K/V in smem

__global__ void attn_kernel(const float* __restrict__ qkv, float* __restrict__ out)
{
    extern __shared__ float sm[];
    float* Ks = sm;                        // 198*65
    float* Vs = Ks + NTOK * KVP;           // 198*65
    float* Qs = Vs + NTOK * KVP;           // 8*64
    float* Ps = Qs + 8 * 64;               // 8*198

    int bh = blockIdx.x;
    int b = bh / HEADS, h = bh % HEADS;
    const float* base = qkv + (size_t)b * NTOK * (3 * EMBED) + h * HEAD_DIM;

    int tid = threadIdx.x;
    for (int idx = tid; idx < NTOK * HEAD_DIM; idx += 256) {
        int t = idx >> 6, d = idx & 63;
        Ks[t * KVP + d] = base[(size_t)t * (3 * EMBED) + EMBED + d];
        Vs[t * KVP + d] = base[(size_t)t * (3 * EMBED) + 2 * EMBED + d];
    }
    __syncthreads();

    int warp = tid >> 5, lane = tid & 31;
    for (int r = warp; r < NTOK; r += 8) {
        // load scaled q row into smem
        Qs[warp * 64 + lane]      = base[(size_t)r * (3 * EMBED) + lane]      * SCALE_F;
        Qs[warp * 64 + 32 + lane] = base[(size_t)r * (3 * EMBED) + 32 + lane] * SCALE_F;
        __syncwarp();

        float s[7];
        float mx = -1e30f;
        const float* qr = Qs + warp * 64;
        #pragma unroll
        for (int c = 0; c < 7; c++) {
            int j = lane + 32 * c;
            float acc = -1e30f;
            if (j < NTOK) {
                const float* kr = Ks + j * KVP;
                acc = 0.f;
                #pragma unroll
                for (int d = 0; d < 64; d++) acc += qr[d] * kr[d];
                mx = fmaxf(mx, acc);
            }
            s[c] = acc;
        }
        #pragma unroll
        for (int o = 16; o > 0; o >>= 1) mx = fmaxf(mx, __shfl_xor_sync(0xffffffffu, mx, o));

        float sum = 0.f;
        #pragma unroll
        for (int c = 0; c < 7; c++) {
            int j = lane + 32 * c;
            if (j < NTOK) { s[c] = expf(s[c] - mx); sum += s[c]; }
            else s[c] = 0.f;
        }
        #pragma unroll
        for (int o = 16; o > 0; o >>= 1) sum += __shfl_xor_sync(0xffffffffu, sum, o);
        float inv = 1.f / sum;

        #pragma unroll
        for (int c = 0; c < 7; c++) {
            int j = lane + 32 * c;
            if (j < NTOK) Ps[warp * NTOK + j] = s[c] * inv;
        }
        __syncwarp();

        float o0 = 0.f, o1 = 0.f;
        const float* pr = Ps + warp * NTOK;
        for (int j = 0; j < NTOK; j++) {
            float p = pr[j];
            o0 += p * Vs[j * KVP + lane];
            o1 += p * Vs[j * KVP + 32 + lane];
        }
        float* op = out + ((size_t)b * NTOK + r) * EMBED + h * HEAD_DIM;
        op[lane]      = o0;
        op[lane + 32] = o1;
        __syncwarp();
    }
}

// ---------------- LayerNorm (exact two-pass variance) ----------------
__global__ void ln_kernel(const float* __restrict__ x, const float* __restrict__ w,
                          const float* __restrict__ bb, float* __restrict__ y)
{
    int row = blockIdx.x;
    const float* xr = x + (size_t)row * EMBED;
    float* yr = y + (size_t)row * EMBED;
    int tid = threadIdx.x;          // 256
    int warp = tid >> 5, lane = tid & 31;
    __shared__ float sh[8];

    float v0 = xr[tid], v1 = xr[tid + 256], v2 = xr[tid + 512];
    float s = v0 + v1 + v2;
    #pragma unroll
    for (int o = 16; o > 0; o >>= 1) s += __shfl_xor_sync(0xffffffffu, s, o);
    if (lane == 0) sh[warp] = s;
    __syncthreads();
    float ts = 0.f;
    #pragma unroll
    for (int i = 0; i < 8; i++) ts += sh[i];
    float mu = ts * (1.f / 768.f);

    float d0 = v0 - mu, d1 = v1 - mu, d2 = v2 - mu;
    float q = d0 * d0 + d1 * d1 + d2 * d2;
    #pragma unroll
    for (int o = 16; o > 0; o >>= 1) q += __shfl_xor_sync(0xffffffffu, q, o);
    __syncthreads();
    if (lane == 0) sh[warp] = q;
    __syncthreads();
    float tq = 0.f;
    #pragma unroll
    for (int i = 0; i < 8; i++) tq += sh[i];
    float inv = rsqrtf(tq * (1.f / 768.f) + 1e-5f);

    yr[tid]       = d0 * inv * w[tid]       + bb[tid];
    yr[tid + 256] = d1 * inv * w[tid + 256] + bb[tid + 256];
    yr[tid + 512] = d2 * inv * w[tid + 512] + bb[tid + 512];
}

// ---------------- host orchestration ----------------
extern "C" void kernel_launch(void* const* d_in, const int* in_sizes, int n_in,
                              void* d_out, int out_size)
{
    const float* x        = (const float*)d_in[0];
    const float* conv_w   = (const float*)d_in[1];
    const float* conv_b   = (const float*)d_in[2];
    const float* pos      = (const float*)d_in[3];
    const float* cls_tok  = (const float*)d_in[4];
    const float* loc_tok  = (const float*)d_in[5];
    const float* ln1_w    = (const float*)d_in[6];
    const float* ln1_b    = (const float*)d_in[7];
    const float* qkv_w    = (const float*)d_in[8];
    const float* proj_w   = (const float*)d_in[9];
    const float* proj_b   = (const float*)d_in[10];
    const float* ln2_w    = (const float*)d_in[11];
    const float* ln2_b    = (const float*)d_in[12];
    const float* fc1_w    = (const float*)d_in[13];
    const float* fc1_b    = (const float*)d_in[14];
    const float* fc2_w    = (const float*)d_in[15];
    const float* fc2_b    = (const float*)d_in[16];
    const float* lnf_w    = (const float*)d_in[17];
    const float* lnf_b    = (const float*)d_in[18];
    float* out = (float*)d_out;

    float *h, *y, *qkv, *att, *hid, *P, *WT;
    cudaGetSymbolAddress((void**)&h,   g_h);
    cudaGetSymbolAddress((void**)&y,   g_y);
    cudaGetSymbolAddress((void**)&qkv, g_qkv);
    cudaGetSymbolAddress((void**)&att, g_att);
    cudaGetSymbolAddress((void**)&hid, g_hid);
    cudaGetSymbolAddress((void**)&P,   g_P);
    cudaGetSymbolAddress((void**)&WT,  g_WT);

    const int ATT_SMEM = (NTOK * KVP * 2 + 8 * 64 + 8 * NTOK) * (int)sizeof(float);
    cudaFuncSetAttribute(attn_kernel, cudaFuncAttributeMaxDynamicSharedMemorySize, ATT_SMEM);

    // patch embed
    transpose768_kernel<<<dim3(24, 24), dim3(32, 8)>>>(conv_w, WT);
    im2col_kernel<<<PROWS, 256>>>(x, P);
    init_tokens_kernel<<<BATCH, EMBED>>>(h, loc_tok, cls_tok);
    sgemm_kernel<<<dim3(EMBED / BN, PROWS / BM), 256>>>(
        P, WT, h, conv_b, nullptr, pos, PROWS, EMBED, EMBED, EPI_PATCH);

    for (int l = 0; l < DEPTH; l++) {
        const float* l1w = ln1_w + (size_t)l * EMBED;
        const float* l1b = ln1_b + (size_t)l * EMBED;
        const float* qw  = qkv_w + (size_t)l * EMBED * 3 * EMBED;
        const float* pw  = proj_w + (size_t)l * EMBED * EMBED;
        const float* pb  = proj_b + (size_t)l * EMBED;
        const float* l2w = ln2_w + (size_t)l * EMBED;
        const float* l2b = ln2_b + (size_t)l * EMBED;
        const float* f1w = fc1_w + (size_t)l * EMBED * HIDDEN;
        const float* f1b = fc1_b + (size_t)l * HIDDEN;
        const float* f2w = fc2_w + (size_t)l * HIDDEN * EMBED;
        const float* f2b = fc2_b + (size_t)l * EMBED;

        ln_kernel<<<TOKENS, 256>>>(h, l1w, l1b, y);
        sgemm_kernel<<<dim3(3 * EMBED / BN, TOKENS / BM), 256>>>(
            y, qw, qkv, nullptr, nullptr, nullptr, TOKENS, 3 * EMBED, EMBED, EPI_NONE);
        attn_kernel<<<BATCH * HEADS, 256, ATT_SMEM>>>(qkv, att);
        sgemm_kernel<<<dim3(EMBED / BN, TOKENS / BM), 256>>>(
            att, pw, h, pb, h, nullptr, TOKENS, EMBED, EMBED, EPI_BIAS_RES);
        ln_kernel<<<TOKENS, 256>>>(h, l2w, l2b, y);
        sgemm_kernel<<<dim3(HIDDEN / BN, TOKENS / BM), 256>>>(
            y, f1w, hid, f1b, nullptr, nullptr, TOKENS, HIDDEN, EMBED, EPI_BIAS_GELU);
        sgemm_kernel<<<dim3(EMBED / BN, TOKENS / BM), 256>>>(
            hid, f2w, h, f2b, h, nullptr, TOKENS, EMBED, HIDDEN, EPI_BIAS_RES);
    }

    ln_kernel<<<TOKENS, 256>>>(h, lnf_w, lnf_b, out);
}